// round 1
// baseline (speedup 1.0000x reference)
#include <cuda_runtime.h>
#include <cuda_bf16.h>
#include <math.h>

#define VV 32000
#define DD 1024
#define LL 6
#define HH 16
#define FFD 4096
#define SS 1024
#define BB 2
#define DK 64
#define MM (BB*SS)   // 2048 rows

// ---------------- scratch (device globals; no allocation) ----------------
__device__ float g_h[MM*DD];
__device__ float g_xn[MM*DD];
__device__ float g_q[MM*DD];
__device__ float g_k[MM*DD];
__device__ float g_v[MM*DD];
__device__ float g_ctx[MM*DD];
__device__ float g_ff[MM*FFD];

// ---------------- embedding + positional encoding ----------------
__global__ void embed_kernel(const int* __restrict__ x, const float* __restrict__ emb,
                             float* __restrict__ h) {
    int idx = blockIdx.x * blockDim.x + threadIdx.x;   // over MM*DD
    int d  = idx & (DD - 1);
    int bs = idx >> 10;            // DD=1024
    int s  = bs & (SS - 1);
    int tok = x[bs];
    int i2 = d & ~1;
    float div = expf(-(float)i2 * (logf(10000.0f) / (float)DD));
    float ang = (float)s * div;
    float pe = (d & 1) ? cosf(ang) : sinf(ang);
    h[idx] = emb[(size_t)tok * DD + d] * 32.0f + pe;   // sqrt(1024)=32
}

// ---------------- layernorm: one block per row ----------------
__global__ void __launch_bounds__(256) ln_kernel(const float* __restrict__ in,
                                                 const float* __restrict__ w,
                                                 const float* __restrict__ b,
                                                 float* __restrict__ out) {
    int row = blockIdx.x;
    int t = threadIdx.x;
    int lane = t & 31, wid = t >> 5;
    __shared__ float red[8];

    float4 x4 = ((const float4*)(in + (size_t)row * DD))[t];
    float s = x4.x + x4.y + x4.z + x4.w;
    #pragma unroll
    for (int o = 16; o; o >>= 1) s += __shfl_xor_sync(0xffffffffu, s, o);
    if (lane == 0) red[wid] = s;
    __syncthreads();
    float tot = red[0]+red[1]+red[2]+red[3]+red[4]+red[5]+red[6]+red[7];
    float mean = tot * (1.0f / DD);
    __syncthreads();

    float d0 = x4.x - mean, d1 = x4.y - mean, d2 = x4.z - mean, d3 = x4.w - mean;
    float vs = d0*d0 + d1*d1 + d2*d2 + d3*d3;
    #pragma unroll
    for (int o = 16; o; o >>= 1) vs += __shfl_xor_sync(0xffffffffu, vs, o);
    if (lane == 0) red[wid] = vs;
    __syncthreads();
    float var = (red[0]+red[1]+red[2]+red[3]+red[4]+red[5]+red[6]+red[7]) * (1.0f / DD);
    float inv = rsqrtf(var + 1e-5f);

    float4 w4 = ((const float4*)w)[t];
    float4 b4 = ((const float4*)b)[t];
    float4 o4;
    o4.x = d0 * inv * w4.x + b4.x;
    o4.y = d1 * inv * w4.y + b4.y;
    o4.z = d2 * inv * w4.z + b4.z;
    o4.w = d3 * inv * w4.w + b4.w;
    ((float4*)(out + (size_t)row * DD))[t] = o4;
}

// ---------------- tiled SGEMM: C[M,N] = A[M,K] @ W[N,K]^T (+bias)(+res)(gelu) ----------------
#define BM 128
#define BN 64
#define BK 16
#define TM 8
#define TN 4

__global__ void __launch_bounds__(256) gemm_kernel(const float* __restrict__ A,
                                                   const float* __restrict__ W,
                                                   const float* __restrict__ bias,
                                                   const float* __restrict__ res,
                                                   float* __restrict__ C,
                                                   int M, int N, int K, int act) {
    __shared__ float As[BK][BM];
    __shared__ float Ws[BK][BN];

    int tid = threadIdx.x;
    int tx = tid & 15;       // 0..15 -> cols
    int ty = tid >> 4;       // 0..15 -> rows
    int m0 = blockIdx.y * BM;
    int n0 = blockIdx.x * BN;

    float acc[TM][TN];
    #pragma unroll
    for (int i = 0; i < TM; i++)
        #pragma unroll
        for (int j = 0; j < TN; j++) acc[i][j] = 0.0f;

    for (int k0 = 0; k0 < K; k0 += BK) {
        // load A tile: 128x16 = 512 float4, 2 per thread; store k-major
        #pragma unroll
        for (int it = 0; it < 2; it++) {
            int lin = tid + it * 256;
            int row = lin >> 2;
            int kq = (lin & 3) << 2;
            float4 va = *(const float4*)&A[(size_t)(m0 + row) * K + k0 + kq];
            As[kq + 0][row] = va.x;
            As[kq + 1][row] = va.y;
            As[kq + 2][row] = va.z;
            As[kq + 3][row] = va.w;
        }
        // load W tile: 64x16 = 256 float4, 1 per thread
        {
            int row = tid >> 2;
            int kq = (tid & 3) << 2;
            float4 vw = *(const float4*)&W[(size_t)(n0 + row) * K + k0 + kq];
            Ws[kq + 0][row] = vw.x;
            Ws[kq + 1][row] = vw.y;
            Ws[kq + 2][row] = vw.z;
            Ws[kq + 3][row] = vw.w;
        }
        __syncthreads();

        #pragma unroll
        for (int kk = 0; kk < BK; kk++) {
            float a[TM], wv[TN];
            #pragma unroll
            for (int i = 0; i < TM; i++) a[i] = As[kk][ty * TM + i];
            #pragma unroll
            for (int j = 0; j < TN; j++) wv[j] = Ws[kk][tx * TN + j];
            #pragma unroll
            for (int i = 0; i < TM; i++)
                #pragma unroll
                for (int j = 0; j < TN; j++)
                    acc[i][j] += a[i] * wv[j];
        }
        __syncthreads();
    }

    #pragma unroll
    for (int i = 0; i < TM; i++) {
        int m = m0 + ty * TM + i;
        #pragma unroll
        for (int j = 0; j < TN; j++) {
            int n = n0 + tx * TN + j;
            float c = acc[i][j];
            if (bias) c += bias[n];
            if (res)  c += res[(size_t)m * N + n];
            if (act)  c = 0.5f * c * (1.0f + erff(c * 0.70710678118654752f));
            C[(size_t)m * N + n] = c;
        }
    }
}

// ---------------- causal attention: one block per (b,h,q) ----------------
__global__ void __launch_bounds__(128) attn_kernel(const float* __restrict__ q,
                                                   const float* __restrict__ k,
                                                   const float* __restrict__ v,
                                                   float* __restrict__ ctx) {
    int bid = blockIdx.x;
    int sq = bid & (SS - 1);
    int bh = bid >> 10;
    int hh = bh & (HH - 1);
    int bb = bh >> 4;

    int tid = threadIdx.x;
    int lane = tid & 31;
    int warp = tid >> 5;

    __shared__ float sc[SS];
    __shared__ float qs[DK];
    __shared__ float red[4];
    __shared__ float cacc[128];

    const size_t base = (size_t)bb * SS * DD + (size_t)hh * DK;

    if (tid < DK) qs[tid] = q[base + (size_t)sq * DD + tid];
    __syncthreads();

    int nk = sq + 1;

    // scores: warp-per-key (coalesced K row loads)
    float lmax = -1e30f;
    for (int j = warp; j < nk; j += 4) {
        const float* kr = k + base + (size_t)j * DD;
        float d = qs[lane] * kr[lane] + qs[lane + 32] * kr[lane + 32];
        #pragma unroll
        for (int o = 16; o; o >>= 1) d += __shfl_xor_sync(0xffffffffu, d, o);
        d *= 0.125f;                           // 1/sqrt(64)
        if (lane == 0) sc[j] = d;
        lmax = fmaxf(lmax, d);
    }
    #pragma unroll
    for (int o = 16; o; o >>= 1) lmax = fmaxf(lmax, __shfl_xor_sync(0xffffffffu, lmax, o));
    if (lane == 0) red[warp] = lmax;
    __syncthreads();
    float gmax = fmaxf(fmaxf(red[0], red[1]), fmaxf(red[2], red[3]));
    __syncthreads();

    // softmax numerator + sum
    float lsum = 0.0f;
    for (int j = tid; j < nk; j += 128) {
        float e = expf(sc[j] - gmax);
        sc[j] = e;
        lsum += e;
    }
    #pragma unroll
    for (int o = 16; o; o >>= 1) lsum += __shfl_xor_sync(0xffffffffu, lsum, o);
    if (lane == 0) red[warp] = lsum;
    __syncthreads();
    float inv = 1.0f / (red[0] + red[1] + red[2] + red[3]);
    __syncthreads();

    // ctx = attn @ V: thread owns (dim = tid&63, key parity = tid>>6)
    int dd = tid & 63;
    int par = tid >> 6;
    float acc = 0.0f;
    for (int j = par; j < nk; j += 2)
        acc += sc[j] * v[base + (size_t)j * DD + dd];
    cacc[tid] = acc;
    __syncthreads();
    if (tid < 64)
        ctx[base + (size_t)sq * DD + tid] = (cacc[tid] + cacc[tid + 64]) * inv;
}

// ---------------- launch ----------------
static void launch_gemm(const float* A, const float* W, const float* bias,
                        const float* res, float* C, int M, int N, int K, int act) {
    dim3 grid(N / BN, M / BM);
    gemm_kernel<<<grid, 256>>>(A, W, bias, res, C, M, N, K, act);
}

extern "C" void kernel_launch(void* const* d_in, const int* in_sizes, int n_in,
                              void* d_out, int out_size) {
    const int*   x     = (const int*)d_in[0];
    const float* emb   = (const float*)d_in[1];
    const float* ln1_w = (const float*)d_in[2];
    const float* ln1_b = (const float*)d_in[3];
    const float* wq_w  = (const float*)d_in[4];
    const float* wq_b  = (const float*)d_in[5];
    const float* wk_w  = (const float*)d_in[6];
    const float* wk_b  = (const float*)d_in[7];
    const float* wv_w  = (const float*)d_in[8];
    const float* wv_b  = (const float*)d_in[9];
    const float* wo_w  = (const float*)d_in[10];
    const float* wo_b  = (const float*)d_in[11];
    const float* ln2_w = (const float*)d_in[12];
    const float* ln2_b = (const float*)d_in[13];
    const float* w1_w  = (const float*)d_in[14];
    const float* w1_b  = (const float*)d_in[15];
    const float* w2_w  = (const float*)d_in[16];
    const float* w2_b  = (const float*)d_in[17];
    const float* lnf_w = (const float*)d_in[18];
    const float* lnf_b = (const float*)d_in[19];
    float* out = (float*)d_out;

    float *h, *xn, *q, *k, *v, *ctx, *ff;
    cudaGetSymbolAddress((void**)&h,   g_h);
    cudaGetSymbolAddress((void**)&xn,  g_xn);
    cudaGetSymbolAddress((void**)&q,   g_q);
    cudaGetSymbolAddress((void**)&k,   g_k);
    cudaGetSymbolAddress((void**)&v,   g_v);
    cudaGetSymbolAddress((void**)&ctx, g_ctx);
    cudaGetSymbolAddress((void**)&ff,  g_ff);

    embed_kernel<<<(MM * DD) / 256, 256>>>(x, emb, h);

    for (int l = 0; l < LL; l++) {
        const float* l1w = ln1_w + (size_t)l * DD;
        const float* l1b = ln1_b + (size_t)l * DD;
        ln_kernel<<<MM, 256>>>(h, l1w, l1b, xn);

        launch_gemm(xn, wq_w + (size_t)l * DD * DD, wq_b + (size_t)l * DD, nullptr, q,   MM, DD, DD, 0);
        launch_gemm(xn, wk_w + (size_t)l * DD * DD, wk_b + (size_t)l * DD, nullptr, k,   MM, DD, DD, 0);
        launch_gemm(xn, wv_w + (size_t)l * DD * DD, wv_b + (size_t)l * DD, nullptr, v,   MM, DD, DD, 0);

        attn_kernel<<<BB * HH * SS, 128>>>(q, k, v, ctx);

        // h = h + ctx @ Wo^T + bo
        launch_gemm(ctx, wo_w + (size_t)l * DD * DD, wo_b + (size_t)l * DD, h, h, MM, DD, DD, 0);

        ln_kernel<<<MM, 256>>>(h, ln2_w + (size_t)l * DD, ln2_b + (size_t)l * DD, xn);

        // ff = gelu(xn @ W1^T + b1)
        launch_gemm(xn, w1_w + (size_t)l * FFD * DD, w1_b + (size_t)l * FFD, nullptr, ff, MM, FFD, DD, 1);
        // h = h + ff @ W2^T + b2
        launch_gemm(ff, w2_w + (size_t)l * DD * FFD, w2_b + (size_t)l * DD, h, h, MM, DD, FFD, 0);
    }

    ln_kernel<<<MM, 256>>>(h, lnf_w, lnf_b, xn);

    // logits = xn @ emb^T   (tied projection, no bias)
    launch_gemm(xn, emb, nullptr, nullptr, out, MM, VV, DD, 0);
}

// round 3
// speedup vs baseline: 2.0524x; 2.0524x over previous
#include <cuda_runtime.h>
#include <cuda_bf16.h>
#include <math.h>
#include <stdint.h>

#define VV 32000
#define DD 1024
#define LL 6
#define HH 16
#define FFD 4096
#define SS 1024
#define BB 2
#define DK 64
#define MM (BB*SS)   // 2048 rows

// ---------------- gemm tile config ----------------
#define BMT 128
#define BNT 128
#define KC 64                       // bf16 per k-chunk (128 bytes/row)
#define AT_BYTES (BMT*128)          // 16384
#define WT_BYTES (BNT*128)          // 16384
#define STAGE_BYTES (2*AT_BYTES + 2*WT_BYTES)   // 65536
#define GSMEM_TOTAL (2*STAGE_BYTES)             // 131072

// ---------------- scratch (device globals; no allocation) ----------------
__device__ float g_h[MM*DD];
__device__ float g_xn[MM*DD];
__device__ float g_q[MM*DD];
__device__ float g_k[MM*DD];
__device__ float g_v[MM*DD];
__device__ float g_ctx[MM*DD];
__device__ float g_ff[MM*FFD];
__device__ __nv_bfloat16 g_ah[MM*FFD];
__device__ __nv_bfloat16 g_al[MM*FFD];
__device__ __nv_bfloat16 g_wh[FFD*DD];
__device__ __nv_bfloat16 g_wl[FFD*DD];
__device__ __nv_bfloat16 g_eh[VV*DD];
__device__ __nv_bfloat16 g_el[VV*DD];

// ---------------- helpers ----------------
__device__ __forceinline__ uint32_t smem_u32(const void* p) {
    uint32_t a;
    asm("{ .reg .u64 t; cvta.to.shared.u64 t, %1; cvt.u32.u64 %0, t; }" : "=r"(a) : "l"(p));
    return a;
}
__device__ __forceinline__ float gelu_f(float x) {
    return 0.5f * x * (1.0f + erff(x * 0.70710678118654752f));
}
__device__ __forceinline__ void cp16(uint32_t dst, const void* src) {
    asm volatile("cp.async.cg.shared.global [%0], [%1], 16;" :: "r"(dst), "l"(src));
}
__device__ __forceinline__ void ldmatrix4(uint32_t* r, uint32_t addr) {
    asm volatile("ldmatrix.sync.aligned.m8n8.x4.shared.b16 {%0,%1,%2,%3}, [%4];"
                 : "=r"(r[0]), "=r"(r[1]), "=r"(r[2]), "=r"(r[3]) : "r"(addr));
}
__device__ __forceinline__ void mma16816(float* c, const uint32_t* a, uint32_t b0, uint32_t b1) {
    asm volatile("mma.sync.aligned.m16n8k16.row.col.f32.bf16.bf16.f32 "
                 "{%0,%1,%2,%3}, {%4,%5,%6,%7}, {%8,%9}, {%0,%1,%2,%3};"
                 : "+f"(c[0]), "+f"(c[1]), "+f"(c[2]), "+f"(c[3])
                 : "r"(a[0]), "r"(a[1]), "r"(a[2]), "r"(a[3]), "r"(b0), "r"(b1));
}

// ---------------- fp32 -> (bf16 hi, bf16 lo) split ----------------
__global__ void split_kernel(const float* __restrict__ x,
                             __nv_bfloat16* __restrict__ h,
                             __nv_bfloat16* __restrict__ l) {
    int i = blockIdx.x * blockDim.x + threadIdx.x;   // per 4 elements
    float4 v = ((const float4*)x)[i];
    __nv_bfloat16 h0 = __float2bfloat16(v.x);
    __nv_bfloat16 h1 = __float2bfloat16(v.y);
    __nv_bfloat16 h2 = __float2bfloat16(v.z);
    __nv_bfloat16 h3 = __float2bfloat16(v.w);
    __nv_bfloat16 l0 = __float2bfloat16(v.x - __bfloat162float(h0));
    __nv_bfloat16 l1 = __float2bfloat16(v.y - __bfloat162float(h1));
    __nv_bfloat16 l2 = __float2bfloat16(v.z - __bfloat162float(h2));
    __nv_bfloat16 l3 = __float2bfloat16(v.w - __bfloat162float(h3));
    __nv_bfloat162 ph0; ph0.x = h0; ph0.y = h1;
    __nv_bfloat162 ph1; ph1.x = h2; ph1.y = h3;
    __nv_bfloat162 pl0; pl0.x = l0; pl0.y = l1;
    __nv_bfloat162 pl1; pl1.x = l2; pl1.y = l3;
    ((__nv_bfloat162*)h)[2*i]   = ph0;
    ((__nv_bfloat162*)h)[2*i+1] = ph1;
    ((__nv_bfloat162*)l)[2*i]   = pl0;
    ((__nv_bfloat162*)l)[2*i+1] = pl1;
}

// ---------------- warp-MMA bf16 split GEMM ----------------
// C[z][M,N] = Ah@Wh^T + Ah@Wl^T + Al@Wh^T  (+bias)(+res)(gelu)
struct GParams {
    const __nv_bfloat16 *Ah, *Al;
    const __nv_bfloat16 *Wh[3], *Wl[3];
    const float *bias[3];
    const float *res[3];
    float *C[3];
    int K, N, act;
};

// swizzled in-tile offset for (row, 16B-unit cu)
__device__ __forceinline__ uint32_t swzoff(int row, int cu) {
    return (uint32_t)(row * 128 + ((cu * 16) ^ ((row & 7) * 16)));
}

__device__ __forceinline__ void stage_loads(uint32_t sstage,
        const __nv_bfloat16* Ah, const __nv_bfloat16* Al,
        const __nv_bfloat16* Wh, const __nv_bfloat16* Wl,
        int m0, int n0, int k0, int K, int tid) {
    #pragma unroll
    for (int t = 0; t < 4; t++) {
        int u = tid + (t << 8);
        int row = u >> 3, cu = u & 7;
        cp16(sstage + swzoff(row, cu), Ah + (size_t)(m0 + row) * K + k0 + cu * 8);
    }
    #pragma unroll
    for (int t = 0; t < 4; t++) {
        int u = tid + (t << 8);
        int row = u >> 3, cu = u & 7;
        cp16(sstage + AT_BYTES + swzoff(row, cu), Al + (size_t)(m0 + row) * K + k0 + cu * 8);
    }
    #pragma unroll
    for (int t = 0; t < 4; t++) {
        int u = tid + (t << 8);
        int row = u >> 3, cu = u & 7;
        cp16(sstage + 2*AT_BYTES + swzoff(row, cu), Wh + (size_t)(n0 + row) * K + k0 + cu * 8);
    }
    #pragma unroll
    for (int t = 0; t < 4; t++) {
        int u = tid + (t << 8);
        int row = u >> 3, cu = u & 7;
        cp16(sstage + 2*AT_BYTES + WT_BYTES + swzoff(row, cu), Wl + (size_t)(n0 + row) * K + k0 + cu * 8);
    }
    asm volatile("cp.async.commit_group;" ::: "memory");
}

// A-fragment ldmatrix: 16x16 tile at (row base r0, byte offset kbyte)
__device__ __forceinline__ void ldA(uint32_t* r, uint32_t base, int r0, int kbyte, int lane) {
    int row = r0 + (lane & 15);
    int x = ((lane >> 4) * 16 + kbyte) ^ ((row & 7) * 16);
    ldmatrix4(r, base + row * 128 + x);
}
// B-fragment ldmatrix: n16 x k16 at (n base nb, byte offset kbyte) -> 2 fragments
__device__ __forceinline__ void ldB(uint32_t* r, uint32_t base, int nb, int kbyte, int lane) {
    int nrow = nb + (lane & 7) + ((lane >> 4) << 3);
    int x = (((lane >> 3) & 1) * 16 + kbyte) ^ ((nrow & 7) * 16);
    ldmatrix4(r, base + nrow * 128 + x);
}

__global__ void __launch_bounds__(256, 1) gemm_bf16_kernel(GParams p) {
    extern __shared__ char smem[];
    const int tid = threadIdx.x;
    const int wid = tid >> 5, lane = tid & 31;
    const int z = blockIdx.z;
    const int m0 = blockIdx.y * BMT, n0 = blockIdx.x * BNT;
    const int K = p.K, N = p.N;
    const __nv_bfloat16* Wh = p.Wh[z];
    const __nv_bfloat16* Wl = p.Wl[z];
    const float* bias = p.bias[z];
    const float* res = p.res[z];
    float* C = p.C[z];
    const uint32_t sb = smem_u32(smem);

    const int wm = (wid >> 1) * 32;     // warp m offset (0,32,64,96)
    const int wn = (wid & 1) * 64;      // warp n offset (0,64)

    float acc[2][8][4];
    #pragma unroll
    for (int i = 0; i < 2; i++)
        #pragma unroll
        for (int j = 0; j < 8; j++)
            #pragma unroll
            for (int q = 0; q < 4; q++) acc[i][j][q] = 0.0f;

    const int nch = K / KC;
    stage_loads(sb,               p.Ah, p.Al, Wh, Wl, m0, n0, 0,  K, tid);
    stage_loads(sb + STAGE_BYTES, p.Ah, p.Al, Wh, Wl, m0, n0, KC, K, tid);

    for (int i = 0; i < nch; i++) {
        asm volatile("cp.async.wait_group 1;" ::: "memory");
        __syncthreads();
        uint32_t st = sb + (i & 1) * STAGE_BYTES;
        uint32_t aH = st, aL = st + AT_BYTES;
        uint32_t wH = st + 2*AT_BYTES, wL = st + 2*AT_BYTES + WT_BYTES;

        #pragma unroll
        for (int ks = 0; ks < 4; ks++) {
            const int kbyte = ks * 32;
            uint32_t ah0[4], ah1[4], al0[4], al1[4];
            ldA(ah0, aH, wm,      kbyte, lane);
            ldA(ah1, aH, wm + 16, kbyte, lane);
            ldA(al0, aL, wm,      kbyte, lane);
            ldA(al1, aL, wm + 16, kbyte, lane);
            uint32_t bh[4][4], bl[4][4];
            #pragma unroll
            for (int g = 0; g < 4; g++) {
                ldB(bh[g], wH, wn + g * 16, kbyte, lane);
                ldB(bl[g], wL, wn + g * 16, kbyte, lane);
            }
            #pragma unroll
            for (int g = 0; g < 4; g++) {
                #pragma unroll
                for (int s = 0; s < 2; s++) {
                    int nj = g * 2 + s;
                    uint32_t h0 = bh[g][s*2], h1 = bh[g][s*2+1];
                    uint32_t l0 = bl[g][s*2], l1 = bl[g][s*2+1];
                    mma16816(acc[0][nj], ah0, h0, h1);
                    mma16816(acc[1][nj], ah1, h0, h1);
                    mma16816(acc[0][nj], al0, h0, h1);
                    mma16816(acc[1][nj], al1, h0, h1);
                    mma16816(acc[0][nj], ah0, l0, l1);
                    mma16816(acc[1][nj], ah1, l0, l1);
                }
            }
        }
        __syncthreads();
        if (i + 2 < nch)
            stage_loads(st, p.Ah, p.Al, Wh, Wl, m0, n0, (i + 2) * KC, K, tid);
    }

    // ---------------- epilogue ----------------
    const int lrow = lane >> 2;
    const int lcol = (lane & 3) * 2;
    #pragma unroll
    for (int mi = 0; mi < 2; mi++) {
        int row0 = m0 + wm + mi * 16 + lrow;
        int row1 = row0 + 8;
        #pragma unroll
        for (int nj = 0; nj < 8; nj++) {
            int col = n0 + wn + nj * 8 + lcol;
            float v00 = acc[mi][nj][0], v01 = acc[mi][nj][1];
            float v10 = acc[mi][nj][2], v11 = acc[mi][nj][3];
            if (bias) {
                float2 b2 = *(const float2*)(bias + col);
                v00 += b2.x; v01 += b2.y; v10 += b2.x; v11 += b2.y;
            }
            if (res) {
                float2 r0 = *(const float2*)(res + (size_t)row0 * N + col);
                float2 r1 = *(const float2*)(res + (size_t)row1 * N + col);
                v00 += r0.x; v01 += r0.y; v10 += r1.x; v11 += r1.y;
            }
            if (p.act) {
                v00 = gelu_f(v00); v01 = gelu_f(v01);
                v10 = gelu_f(v10); v11 = gelu_f(v11);
            }
            *(float2*)(C + (size_t)row0 * N + col) = make_float2(v00, v01);
            *(float2*)(C + (size_t)row1 * N + col) = make_float2(v10, v11);
        }
    }
}

// ---------------- embedding + positional encoding ----------------
__global__ void embed_kernel(const int* __restrict__ x, const float* __restrict__ emb,
                             float* __restrict__ h) {
    int idx = blockIdx.x * blockDim.x + threadIdx.x;
    int d  = idx & (DD - 1);
    int bs = idx >> 10;
    int s  = bs & (SS - 1);
    int tok = x[bs];
    int i2 = d & ~1;
    float div = expf(-(float)i2 * (logf(10000.0f) / (float)DD));
    float ang = (float)s * div;
    float pe = (d & 1) ? cosf(ang) : sinf(ang);
    h[idx] = emb[(size_t)tok * DD + d] * 32.0f + pe;
}

// ---------------- layernorm ----------------
__global__ void __launch_bounds__(256) ln_kernel(const float* __restrict__ in,
                                                 const float* __restrict__ w,
                                                 const float* __restrict__ b,
                                                 float* __restrict__ out) {
    int row = blockIdx.x;
    int t = threadIdx.x;
    int lane = t & 31, wid = t >> 5;
    __shared__ float red[8];

    float4 x4 = ((const float4*)(in + (size_t)row * DD))[t];
    float s = x4.x + x4.y + x4.z + x4.w;
    #pragma unroll
    for (int o = 16; o; o >>= 1) s += __shfl_xor_sync(0xffffffffu, s, o);
    if (lane == 0) red[wid] = s;
    __syncthreads();
    float tot = red[0]+red[1]+red[2]+red[3]+red[4]+red[5]+red[6]+red[7];
    float mean = tot * (1.0f / DD);
    __syncthreads();

    float d0 = x4.x - mean, d1 = x4.y - mean, d2 = x4.z - mean, d3 = x4.w - mean;
    float vs = d0*d0 + d1*d1 + d2*d2 + d3*d3;
    #pragma unroll
    for (int o = 16; o; o >>= 1) vs += __shfl_xor_sync(0xffffffffu, vs, o);
    if (lane == 0) red[wid] = vs;
    __syncthreads();
    float var = (red[0]+red[1]+red[2]+red[3]+red[4]+red[5]+red[6]+red[7]) * (1.0f / DD);
    float inv = rsqrtf(var + 1e-5f);

    float4 w4 = ((const float4*)w)[t];
    float4 b4 = ((const float4*)b)[t];
    float4 o4;
    o4.x = d0 * inv * w4.x + b4.x;
    o4.y = d1 * inv * w4.y + b4.y;
    o4.z = d2 * inv * w4.z + b4.z;
    o4.w = d3 * inv * w4.w + b4.w;
    ((float4*)(out + (size_t)row * DD))[t] = o4;
}

// ---------------- causal attention: one block per (b,h,q) ----------------
__global__ void __launch_bounds__(128) attn_kernel(const float* __restrict__ q,
                                                   const float* __restrict__ k,
                                                   const float* __restrict__ v,
                                                   float* __restrict__ ctx) {
    int bid = blockIdx.x;
    int sq = bid & (SS - 1);
    int bh = bid >> 10;
    int hh = bh & (HH - 1);
    int bb = bh >> 4;

    int tid = threadIdx.x;
    int lane = tid & 31;
    int warp = tid >> 5;

    __shared__ float sc[SS];
    __shared__ float qs[DK];
    __shared__ float red[4];
    __shared__ float cacc[128];

    const size_t base = (size_t)bb * SS * DD + (size_t)hh * DK;

    if (tid < DK) qs[tid] = q[base + (size_t)sq * DD + tid];
    __syncthreads();

    int nk = sq + 1;

    float lmax = -1e30f;
    for (int j = warp; j < nk; j += 4) {
        const float* kr = k + base + (size_t)j * DD;
        float d = qs[lane] * kr[lane] + qs[lane + 32] * kr[lane + 32];
        #pragma unroll
        for (int o = 16; o; o >>= 1) d += __shfl_xor_sync(0xffffffffu, d, o);
        d *= 0.125f;
        if (lane == 0) sc[j] = d;
        lmax = fmaxf(lmax, d);
    }
    #pragma unroll
    for (int o = 16; o; o >>= 1) lmax = fmaxf(lmax, __shfl_xor_sync(0xffffffffu, lmax, o));
    if (lane == 0) red[warp] = lmax;
    __syncthreads();
    float gmax = fmaxf(fmaxf(red[0], red[1]), fmaxf(red[2], red[3]));
    __syncthreads();

    float lsum = 0.0f;
    for (int j = tid; j < nk; j += 128) {
        float e = expf(sc[j] - gmax);
        sc[j] = e;
        lsum += e;
    }
    #pragma unroll
    for (int o = 16; o; o >>= 1) lsum += __shfl_xor_sync(0xffffffffu, lsum, o);
    if (lane == 0) red[warp] = lsum;
    __syncthreads();
    float inv = 1.0f / (red[0] + red[1] + red[2] + red[3]);
    __syncthreads();

    int dd = tid & 63;
    int par = tid >> 6;
    float acc = 0.0f;
    for (int j = par; j < nk; j += 2)
        acc += sc[j] * v[base + (size_t)j * DD + dd];
    cacc[tid] = acc;
    __syncthreads();
    if (tid < 64)
        ctx[base + (size_t)sq * DD + tid] = (cacc[tid] + cacc[tid + 64]) * inv;
}

// ---------------- host-side launch helpers ----------------
static void launch_split(const float* x, __nv_bfloat16* h, __nv_bfloat16* l, size_t n) {
    split_kernel<<<(unsigned)(n / 4 / 256), 256>>>(x, h, l);
}

static void launch_gemm1(const __nv_bfloat16* Ah, const __nv_bfloat16* Al,
                         const __nv_bfloat16* Wh, const __nv_bfloat16* Wl,
                         const float* bias, const float* res, float* C,
                         int K, int N, int act) {
    GParams p{};
    p.Ah = Ah; p.Al = Al;
    p.Wh[0] = Wh; p.Wl[0] = Wl; p.bias[0] = bias; p.res[0] = res; p.C[0] = C;
    p.K = K; p.N = N; p.act = act;
    dim3 grid(N / BNT, MM / BMT, 1);
    gemm_bf16_kernel<<<grid, 256, GSMEM_TOTAL>>>(p);
}

extern "C" void kernel_launch(void* const* d_in, const int* in_sizes, int n_in,
                              void* d_out, int out_size) {
    const int*   x     = (const int*)d_in[0];
    const float* emb   = (const float*)d_in[1];
    const float* ln1_w = (const float*)d_in[2];
    const float* ln1_b = (const float*)d_in[3];
    const float* wq_w  = (const float*)d_in[4];
    const float* wq_b  = (const float*)d_in[5];
    const float* wk_w  = (const float*)d_in[6];
    const float* wk_b  = (const float*)d_in[7];
    const float* wv_w  = (const float*)d_in[8];
    const float* wv_b  = (const float*)d_in[9];
    const float* wo_w  = (const float*)d_in[10];
    const float* wo_b  = (const float*)d_in[11];
    const float* ln2_w = (const float*)d_in[12];
    const float* ln2_b = (const float*)d_in[13];
    const float* w1_w  = (const float*)d_in[14];
    const float* w1_b  = (const float*)d_in[15];
    const float* w2_w  = (const float*)d_in[16];
    const float* w2_b  = (const float*)d_in[17];
    const float* lnf_w = (const float*)d_in[18];
    const float* lnf_b = (const float*)d_in[19];
    float* out = (float*)d_out;

    cudaFuncSetAttribute(gemm_bf16_kernel, cudaFuncAttributeMaxDynamicSharedMemorySize,
                         GSMEM_TOTAL);

    float *h, *xn, *q, *k, *v, *ctx, *ff;
    __nv_bfloat16 *ah, *al, *wh, *wl, *eh, *el;
    cudaGetSymbolAddress((void**)&h,   g_h);
    cudaGetSymbolAddress((void**)&xn,  g_xn);
    cudaGetSymbolAddress((void**)&q,   g_q);
    cudaGetSymbolAddress((void**)&k,   g_k);
    cudaGetSymbolAddress((void**)&v,   g_v);
    cudaGetSymbolAddress((void**)&ctx, g_ctx);
    cudaGetSymbolAddress((void**)&ff,  g_ff);
    cudaGetSymbolAddress((void**)&ah,  g_ah);
    cudaGetSymbolAddress((void**)&al,  g_al);
    cudaGetSymbolAddress((void**)&wh,  g_wh);
    cudaGetSymbolAddress((void**)&wl,  g_wl);
    cudaGetSymbolAddress((void**)&eh,  g_eh);
    cudaGetSymbolAddress((void**)&el,  g_el);

    // split embedding once per call (tied output weights)
    launch_split(emb, eh, el, (size_t)VV * DD);

    embed_kernel<<<(MM * DD) / 256, 256>>>(x, emb, h);

    for (int l = 0; l < LL; l++) {
        size_t wdd = (size_t)l * DD * DD;
        ln_kernel<<<MM, 256>>>(h, ln1_w + (size_t)l * DD, ln1_b + (size_t)l * DD, xn);
        launch_split(xn, ah, al, (size_t)MM * DD);
        launch_split(wq_w + wdd, wh,             wl,             (size_t)DD * DD);
        launch_split(wk_w + wdd, wh + DD*DD,     wl + DD*DD,     (size_t)DD * DD);
        launch_split(wv_w + wdd, wh + 2*DD*DD,   wl + 2*DD*DD,   (size_t)DD * DD);

        {   // batched QKV gemm (z = 0,1,2)
            GParams p{};
            p.Ah = ah; p.Al = al;
            p.Wh[0] = wh;            p.Wl[0] = wl;
            p.Wh[1] = wh + DD*DD;    p.Wl[1] = wl + DD*DD;
            p.Wh[2] = wh + 2*DD*DD;  p.Wl[2] = wl + 2*DD*DD;
            p.bias[0] = wq_b + (size_t)l * DD;
            p.bias[1] = wk_b + (size_t)l * DD;
            p.bias[2] = wv_b + (size_t)l * DD;
            p.res[0] = p.res[1] = p.res[2] = nullptr;
            p.C[0] = q; p.C[1] = k; p.C[2] = v;
            p.K = DD; p.N = DD; p.act = 0;
            dim3 grid(DD / BNT, MM / BMT, 3);
            gemm_bf16_kernel<<<grid, 256, GSMEM_TOTAL>>>(p);
        }

        attn_kernel<<<BB * HH * SS, 128>>>(q, k, v, ctx);

        // h = h + ctx @ Wo^T + bo
        launch_split(ctx, ah, al, (size_t)MM * DD);
        launch_split(wo_w + wdd, wh, wl, (size_t)DD * DD);
        launch_gemm1(ah, al, wh, wl, wo_b + (size_t)l * DD, h, h, DD, DD, 0);

        ln_kernel<<<MM, 256>>>(h, ln2_w + (size_t)l * DD, ln2_b + (size_t)l * DD, xn);

        // ff = gelu(xn @ W1^T + b1)
        launch_split(xn, ah, al, (size_t)MM * DD);
        launch_split(w1_w + (size_t)l * FFD * DD, wh, wl, (size_t)FFD * DD);
        launch_gemm1(ah, al, wh, wl, w1_b + (size_t)l * FFD, nullptr, ff, DD, FFD, 1);

        // h = h + ff @ W2^T + b2
        launch_split(ff, ah, al, (size_t)MM * FFD);
        launch_split(w2_w + (size_t)l * DD * FFD, wh, wl, (size_t)DD * FFD);
        launch_gemm1(ah, al, wh, wl, w2_b + (size_t)l * DD, h, h, FFD, DD, 0);
    }

    ln_kernel<<<MM, 256>>>(h, lnf_w, lnf_b, xn);

    // logits = xn @ emb^T (tied projection, no bias)
    launch_split(xn, ah, al, (size_t)MM * DD);
    launch_gemm1(ah, al, eh, el, nullptr, nullptr, out, DD, VV, 0);
}

// round 4
// speedup vs baseline: 2.9798x; 1.4519x over previous
#include <cuda_runtime.h>
#include <cuda_bf16.h>
#include <math.h>
#include <stdint.h>

#define VV 32000
#define DD 1024
#define LL 6
#define HH 16
#define FFD 4096
#define SS 1024
#define BB 2
#define DK 64
#define MM (BB*SS)   // 2048 rows

// ---------------- gemm tile config ----------------
#define BMT 128
#define BNT 128
#define KC 64                       // bf16 per k-chunk (128 bytes/row)
#define AT_BYTES (BMT*128)          // 16384
#define WT_BYTES (BNT*128)          // 16384
#define STAGE_BYTES (2*AT_BYTES + 2*WT_BYTES)   // 65536
#define NSTAGE 3
#define GSMEM_TOTAL (NSTAGE*STAGE_BYTES)        // 196608

// ---------------- attention config ----------------
#define QT 64
#define ASM_FLOATS (3*64*68 + 64*64)            // Qs,Kt,Vt (stride68) + Ss
#define ASM_BYTES (ASM_FLOATS*4)                // 68608

// ---------------- scratch (device globals; no allocation) ----------------
__device__ float g_h[MM*DD];
__device__ float g_q[MM*DD];
__device__ float g_k[MM*DD];
__device__ float g_v[MM*DD];
__device__ __nv_bfloat16 g_ah[MM*DD];     // activation hi (LN / attn outputs)
__device__ __nv_bfloat16 g_al[MM*DD];     // activation lo
__device__ __nv_bfloat16 g_bh[MM*FFD];    // ff hi
__device__ __nv_bfloat16 g_bl[MM*FFD];    // ff lo
__device__ __nv_bfloat16 g_wh[FFD*DD];    // weight hi
__device__ __nv_bfloat16 g_wl[FFD*DD];    // weight lo
__device__ __nv_bfloat16 g_eh[VV*DD];     // embedding hi
__device__ __nv_bfloat16 g_el[VV*DD];     // embedding lo

// ---------------- helpers ----------------
__device__ __forceinline__ uint32_t smem_u32(const void* p) {
    uint32_t a;
    asm("{ .reg .u64 t; cvta.to.shared.u64 t, %1; cvt.u32.u64 %0, t; }" : "=r"(a) : "l"(p));
    return a;
}
__device__ __forceinline__ float gelu_f(float x) {
    return 0.5f * x * (1.0f + erff(x * 0.70710678118654752f));
}
__device__ __forceinline__ void cp16(uint32_t dst, const void* src) {
    asm volatile("cp.async.cg.shared.global [%0], [%1], 16;" :: "r"(dst), "l"(src));
}
__device__ __forceinline__ void ldmatrix4(uint32_t* r, uint32_t addr) {
    asm volatile("ldmatrix.sync.aligned.m8n8.x4.shared.b16 {%0,%1,%2,%3}, [%4];"
                 : "=r"(r[0]), "=r"(r[1]), "=r"(r[2]), "=r"(r[3]) : "r"(addr));
}
__device__ __forceinline__ void mma16816(float* c, const uint32_t* a, uint32_t b0, uint32_t b1) {
    asm volatile("mma.sync.aligned.m16n8k16.row.col.f32.bf16.bf16.f32 "
                 "{%0,%1,%2,%3}, {%4,%5,%6,%7}, {%8,%9}, {%0,%1,%2,%3};"
                 : "+f"(c[0]), "+f"(c[1]), "+f"(c[2]), "+f"(c[3])
                 : "r"(a[0]), "r"(a[1]), "r"(a[2]), "r"(a[3]), "r"(b0), "r"(b1));
}
__device__ __forceinline__ __nv_bfloat162 split_hi2(float a, float b) {
    __nv_bfloat162 r; r.x = __float2bfloat16(a); r.y = __float2bfloat16(b); return r;
}
__device__ __forceinline__ __nv_bfloat162 split_lo2(float a, float b, __nv_bfloat162 h) {
    __nv_bfloat162 r;
    r.x = __float2bfloat16(a - __bfloat162float(h.x));
    r.y = __float2bfloat16(b - __bfloat162float(h.y));
    return r;
}

// ---------------- fp32 -> (bf16 hi, bf16 lo) split (weights/embedding) ----------------
__global__ void split_kernel(const float* __restrict__ x,
                             __nv_bfloat16* __restrict__ h,
                             __nv_bfloat16* __restrict__ l) {
    int i = blockIdx.x * blockDim.x + threadIdx.x;   // per 4 elements
    float4 v = ((const float4*)x)[i];
    __nv_bfloat162 h0 = split_hi2(v.x, v.y);
    __nv_bfloat162 h1 = split_hi2(v.z, v.w);
    __nv_bfloat162 l0 = split_lo2(v.x, v.y, h0);
    __nv_bfloat162 l1 = split_lo2(v.z, v.w, h1);
    ((__nv_bfloat162*)h)[2*i]   = h0;
    ((__nv_bfloat162*)h)[2*i+1] = h1;
    ((__nv_bfloat162*)l)[2*i]   = l0;
    ((__nv_bfloat162*)l)[2*i+1] = l1;
}

// ---------------- warp-MMA bf16 split GEMM ----------------
// C[z][M,N] = Ah@Wh^T + Ah@Wl^T + Al@Wh^T  (+bias)(+res)(gelu)(fp32 or bf16-split out)
struct GParams {
    const __nv_bfloat16 *Ah, *Al;
    const __nv_bfloat16 *Wh[3], *Wl[3];
    const float *bias[3];
    const float *res[3];
    float *C[3];
    __nv_bfloat16 *Ch, *Cl;     // if nonnull: write bf16 hi/lo instead of fp32
    int K, N, act;
};

__device__ __forceinline__ uint32_t swzoff(int row, int cu) {
    return (uint32_t)(row * 128 + ((cu * 16) ^ ((row & 7) * 16)));
}

__device__ __forceinline__ void stage_loads(uint32_t sstage,
        const __nv_bfloat16* Ah, const __nv_bfloat16* Al,
        const __nv_bfloat16* Wh, const __nv_bfloat16* Wl,
        int m0, int n0, int k0, int K, int tid) {
    #pragma unroll
    for (int t = 0; t < 4; t++) {
        int u = tid + (t << 8);
        int row = u >> 3, cu = u & 7;
        cp16(sstage + swzoff(row, cu), Ah + (size_t)(m0 + row) * K + k0 + cu * 8);
    }
    #pragma unroll
    for (int t = 0; t < 4; t++) {
        int u = tid + (t << 8);
        int row = u >> 3, cu = u & 7;
        cp16(sstage + AT_BYTES + swzoff(row, cu), Al + (size_t)(m0 + row) * K + k0 + cu * 8);
    }
    #pragma unroll
    for (int t = 0; t < 4; t++) {
        int u = tid + (t << 8);
        int row = u >> 3, cu = u & 7;
        cp16(sstage + 2*AT_BYTES + swzoff(row, cu), Wh + (size_t)(n0 + row) * K + k0 + cu * 8);
    }
    #pragma unroll
    for (int t = 0; t < 4; t++) {
        int u = tid + (t << 8);
        int row = u >> 3, cu = u & 7;
        cp16(sstage + 2*AT_BYTES + WT_BYTES + swzoff(row, cu), Wl + (size_t)(n0 + row) * K + k0 + cu * 8);
    }
    asm volatile("cp.async.commit_group;" ::: "memory");
}

__device__ __forceinline__ void ldA(uint32_t* r, uint32_t base, int r0, int kbyte, int lane) {
    int row = r0 + (lane & 15);
    int x = ((lane >> 4) * 16 + kbyte) ^ ((row & 7) * 16);
    ldmatrix4(r, base + row * 128 + x);
}
__device__ __forceinline__ void ldB(uint32_t* r, uint32_t base, int nb, int kbyte, int lane) {
    int nrow = nb + (lane & 7) + ((lane >> 4) << 3);
    int x = (((lane >> 3) & 1) * 16 + kbyte) ^ ((nrow & 7) * 16);
    ldmatrix4(r, base + nrow * 128 + x);
}

__global__ void __launch_bounds__(256, 1) gemm_bf16_kernel(GParams p) {
    extern __shared__ char smem[];
    const int tid = threadIdx.x;
    const int wid = tid >> 5, lane = tid & 31;
    const int z = blockIdx.z;
    const int m0 = blockIdx.y * BMT, n0 = blockIdx.x * BNT;
    const int K = p.K, N = p.N;
    const __nv_bfloat16* Wh = p.Wh[z];
    const __nv_bfloat16* Wl = p.Wl[z];
    const float* bias = p.bias[z];
    const float* res = p.res[z];
    float* C = p.C[z];
    const uint32_t sb = smem_u32(smem);

    const int wm = (wid >> 1) * 32;
    const int wn = (wid & 1) * 64;

    float acc[2][8][4];
    #pragma unroll
    for (int i = 0; i < 2; i++)
        #pragma unroll
        for (int j = 0; j < 8; j++)
            #pragma unroll
            for (int q = 0; q < 4; q++) acc[i][j][q] = 0.0f;

    const int nch = K / KC;
    stage_loads(sb,                 p.Ah, p.Al, Wh, Wl, m0, n0, 0,    K, tid);
    stage_loads(sb +   STAGE_BYTES, p.Ah, p.Al, Wh, Wl, m0, n0, KC,   K, tid);
    stage_loads(sb + 2*STAGE_BYTES, p.Ah, p.Al, Wh, Wl, m0, n0, 2*KC, K, tid);

    for (int i = 0; i < nch; i++) {
        asm volatile("cp.async.wait_group 2;" ::: "memory");
        __syncthreads();
        uint32_t st = sb + (uint32_t)(i % 3) * STAGE_BYTES;
        uint32_t aH = st, aL = st + AT_BYTES;
        uint32_t wH = st + 2*AT_BYTES, wL = st + 2*AT_BYTES + WT_BYTES;

        #pragma unroll
        for (int ks = 0; ks < 4; ks++) {
            const int kbyte = ks * 32;
            uint32_t ah0[4], ah1[4], al0[4], al1[4];
            ldA(ah0, aH, wm,      kbyte, lane);
            ldA(ah1, aH, wm + 16, kbyte, lane);
            ldA(al0, aL, wm,      kbyte, lane);
            ldA(al1, aL, wm + 16, kbyte, lane);
            uint32_t bh[4][4], bl[4][4];
            #pragma unroll
            for (int g = 0; g < 4; g++) {
                ldB(bh[g], wH, wn + g * 16, kbyte, lane);
                ldB(bl[g], wL, wn + g * 16, kbyte, lane);
            }
            #pragma unroll
            for (int g = 0; g < 4; g++) {
                #pragma unroll
                for (int s = 0; s < 2; s++) {
                    int nj = g * 2 + s;
                    uint32_t h0 = bh[g][s*2], h1 = bh[g][s*2+1];
                    uint32_t l0 = bl[g][s*2], l1 = bl[g][s*2+1];
                    mma16816(acc[0][nj], ah0, h0, h1);
                    mma16816(acc[1][nj], ah1, h0, h1);
                    mma16816(acc[0][nj], al0, h0, h1);
                    mma16816(acc[1][nj], al1, h0, h1);
                    mma16816(acc[0][nj], ah0, l0, l1);
                    mma16816(acc[1][nj], ah1, l0, l1);
                }
            }
        }
        __syncthreads();
        if (i + 3 < nch)
            stage_loads(st, p.Ah, p.Al, Wh, Wl, m0, n0, (i + 3) * KC, K, tid);
    }

    // ---------------- epilogue ----------------
    const int lrow = lane >> 2;
    const int lcol = (lane & 3) * 2;
    #pragma unroll
    for (int mi = 0; mi < 2; mi++) {
        int row0 = m0 + wm + mi * 16 + lrow;
        int row1 = row0 + 8;
        #pragma unroll
        for (int nj = 0; nj < 8; nj++) {
            int col = n0 + wn + nj * 8 + lcol;
            float v00 = acc[mi][nj][0], v01 = acc[mi][nj][1];
            float v10 = acc[mi][nj][2], v11 = acc[mi][nj][3];
            if (bias) {
                float2 b2 = *(const float2*)(bias + col);
                v00 += b2.x; v01 += b2.y; v10 += b2.x; v11 += b2.y;
            }
            if (res) {
                float2 r0 = *(const float2*)(res + (size_t)row0 * N + col);
                float2 r1 = *(const float2*)(res + (size_t)row1 * N + col);
                v00 += r0.x; v01 += r0.y; v10 += r1.x; v11 += r1.y;
            }
            if (p.act) {
                v00 = gelu_f(v00); v01 = gelu_f(v01);
                v10 = gelu_f(v10); v11 = gelu_f(v11);
            }
            if (p.Ch) {
                __nv_bfloat162 H0 = split_hi2(v00, v01);
                __nv_bfloat162 H1 = split_hi2(v10, v11);
                __nv_bfloat162 L0 = split_lo2(v00, v01, H0);
                __nv_bfloat162 L1 = split_lo2(v10, v11, H1);
                *(__nv_bfloat162*)(p.Ch + (size_t)row0 * N + col) = H0;
                *(__nv_bfloat162*)(p.Cl + (size_t)row0 * N + col) = L0;
                *(__nv_bfloat162*)(p.Ch + (size_t)row1 * N + col) = H1;
                *(__nv_bfloat162*)(p.Cl + (size_t)row1 * N + col) = L1;
            } else {
                *(float2*)(C + (size_t)row0 * N + col) = make_float2(v00, v01);
                *(float2*)(C + (size_t)row1 * N + col) = make_float2(v10, v11);
            }
        }
    }
}

// ---------------- embedding + positional encoding ----------------
__global__ void embed_kernel(const int* __restrict__ x, const float* __restrict__ emb,
                             float* __restrict__ h) {
    int idx = blockIdx.x * blockDim.x + threadIdx.x;
    int d  = idx & (DD - 1);
    int bs = idx >> 10;
    int s  = bs & (SS - 1);
    int tok = x[bs];
    int i2 = d & ~1;
    float div = expf(-(float)i2 * (logf(10000.0f) / (float)DD));
    float ang = (float)s * div;
    float pe = (d & 1) ? cosf(ang) : sinf(ang);
    h[idx] = emb[(size_t)tok * DD + d] * 32.0f + pe;
}

// ---------------- layernorm (writes bf16 hi/lo split) ----------------
__global__ void __launch_bounds__(256) ln_kernel(const float* __restrict__ in,
                                                 const float* __restrict__ w,
                                                 const float* __restrict__ b,
                                                 __nv_bfloat16* __restrict__ oh,
                                                 __nv_bfloat16* __restrict__ ol) {
    int row = blockIdx.x;
    int t = threadIdx.x;
    int lane = t & 31, wid = t >> 5;
    __shared__ float red[8];

    float4 x4 = ((const float4*)(in + (size_t)row * DD))[t];
    float s = x4.x + x4.y + x4.z + x4.w;
    #pragma unroll
    for (int o = 16; o; o >>= 1) s += __shfl_xor_sync(0xffffffffu, s, o);
    if (lane == 0) red[wid] = s;
    __syncthreads();
    float tot = red[0]+red[1]+red[2]+red[3]+red[4]+red[5]+red[6]+red[7];
    float mean = tot * (1.0f / DD);
    __syncthreads();

    float d0 = x4.x - mean, d1 = x4.y - mean, d2 = x4.z - mean, d3 = x4.w - mean;
    float vs = d0*d0 + d1*d1 + d2*d2 + d3*d3;
    #pragma unroll
    for (int o = 16; o; o >>= 1) vs += __shfl_xor_sync(0xffffffffu, vs, o);
    if (lane == 0) red[wid] = vs;
    __syncthreads();
    float var = (red[0]+red[1]+red[2]+red[3]+red[4]+red[5]+red[6]+red[7]) * (1.0f / DD);
    float inv = rsqrtf(var + 1e-5f);

    float4 w4 = ((const float4*)w)[t];
    float4 b4 = ((const float4*)b)[t];
    float o0 = d0 * inv * w4.x + b4.x;
    float o1 = d1 * inv * w4.y + b4.y;
    float o2 = d2 * inv * w4.z + b4.z;
    float o3 = d3 * inv * w4.w + b4.w;
    __nv_bfloat162 H0 = split_hi2(o0, o1), H1 = split_hi2(o2, o3);
    __nv_bfloat162 L0 = split_lo2(o0, o1, H0), L1 = split_lo2(o2, o3, H1);
    ((__nv_bfloat162*)(oh + (size_t)row * DD))[2*t]   = H0;
    ((__nv_bfloat162*)(oh + (size_t)row * DD))[2*t+1] = H1;
    ((__nv_bfloat162*)(ol + (size_t)row * DD))[2*t]   = L0;
    ((__nv_bfloat162*)(ol + (size_t)row * DD))[2*t+1] = L1;
}

// ---------------- tiled flash attention ----------------
// grid: (SS/QT, BB*HH); 256 threads. Thread owns 2 q-rows x (8 keys | 8 dims).
__global__ void __launch_bounds__(256) attn_kernel(const float* __restrict__ q,
                                                   const float* __restrict__ k,
                                                   const float* __restrict__ v,
                                                   __nv_bfloat16* __restrict__ ch,
                                                   __nv_bfloat16* __restrict__ cl) {
    extern __shared__ float sm[];
    float* Qs = sm;                  // [QT][68]
    float* Kt = Qs + QT*68;          // [64][68]
    float* Vt = Kt + 64*68;          // [64][68]
    float* Ss = Vt + 64*68;          // [QT][64]

    const int qt = blockIdx.x;
    const int bh = blockIdx.y;
    const int hh = bh & (HH - 1);
    const int bb = bh >> 4;
    const int q0 = qt * QT;
    const size_t base = (size_t)bb * SS * DD + (size_t)hh * DK;

    const int tid = threadIdx.x;
    const int rp  = tid >> 3;      // 0..31
    const int oct = tid & 7;       // 0..7
    const int r0 = rp * 2, r1 = r0 + 1;

    // load Q tile, pre-scaled by 1/sqrt(DK)
    for (int t = tid; t < QT * 16; t += 256) {
        int row = t >> 4, c4 = t & 15;
        float4 vq = *(const float4*)(q + base + (size_t)(q0 + row) * DD + c4 * 4);
        vq.x *= 0.125f; vq.y *= 0.125f; vq.z *= 0.125f; vq.w *= 0.125f;
        *(float4*)(Qs + row * 68 + c4 * 4) = vq;
    }

    float m0 = -1e30f, m1 = -1e30f, l0 = 0.0f, l1 = 0.0f;
    float c0[8], c1[8];
    #pragma unroll
    for (int i = 0; i < 8; i++) { c0[i] = 0.0f; c1[i] = 0.0f; }

    const int ntiles = qt + 1;
    for (int t = 0; t < ntiles; t++) {
        const int k0 = t * 64;
        __syncthreads();   // previous tile fully consumed before overwrite
        for (int u = tid; u < 64 * 16; u += 256) {
            int row = u >> 4, c4 = u & 15;
            *(float4*)(Kt + row * 68 + c4 * 4) =
                *(const float4*)(k + base + (size_t)(k0 + row) * DD + c4 * 4);
            *(float4*)(Vt + row * 68 + c4 * 4) =
                *(const float4*)(v + base + (size_t)(k0 + row) * DD + c4 * 4);
        }
        __syncthreads();

        // scores: thread's keys are j = kk*8 + oct (interleaved for bank spread)
        float s0[8], s1[8];
        #pragma unroll
        for (int kk = 0; kk < 8; kk++) { s0[kk] = 0.0f; s1[kk] = 0.0f; }
        #pragma unroll
        for (int d4 = 0; d4 < 16; d4++) {
            float4 qa = *(float4*)(Qs + r0 * 68 + d4 * 4);
            float4 qb = *(float4*)(Qs + r1 * 68 + d4 * 4);
            #pragma unroll
            for (int kk = 0; kk < 8; kk++) {
                float4 kv = *(float4*)(Kt + (kk * 8 + oct) * 68 + d4 * 4);
                s0[kk] += qa.x*kv.x + qa.y*kv.y + qa.z*kv.z + qa.w*kv.w;
                s1[kk] += qb.x*kv.x + qb.y*kv.y + qb.z*kv.z + qb.w*kv.w;
            }
        }
        const bool last = (t == qt);
        if (last) {
            #pragma unroll
            for (int kk = 0; kk < 8; kk++) {
                int j = kk * 8 + oct;
                if (j > r0) s0[kk] = -1e30f;
                if (j > r1) s1[kk] = -1e30f;
            }
        }
        // row max (reduce over the 8-lane octave group)
        float tm0 = s0[0], tm1 = s1[0];
        #pragma unroll
        for (int kk = 1; kk < 8; kk++) { tm0 = fmaxf(tm0, s0[kk]); tm1 = fmaxf(tm1, s1[kk]); }
        #pragma unroll
        for (int o = 1; o < 8; o <<= 1) {
            tm0 = fmaxf(tm0, __shfl_xor_sync(0xffffffffu, tm0, o));
            tm1 = fmaxf(tm1, __shfl_xor_sync(0xffffffffu, tm1, o));
        }
        float m0n = fmaxf(m0, tm0), m1n = fmaxf(m1, tm1);
        float a0 = expf(m0 - m0n), a1 = expf(m1 - m1n);
        float sum0 = 0.0f, sum1 = 0.0f;
        #pragma unroll
        for (int kk = 0; kk < 8; kk++) {
            int j = kk * 8 + oct;
            float e0 = expf(s0[kk] - m0n);
            float e1 = expf(s1[kk] - m1n);
            Ss[r0 * 64 + j] = e0;
            Ss[r1 * 64 + j] = e1;
            sum0 += e0; sum1 += e1;
        }
        #pragma unroll
        for (int o = 1; o < 8; o <<= 1) {
            sum0 += __shfl_xor_sync(0xffffffffu, sum0, o);
            sum1 += __shfl_xor_sync(0xffffffffu, sum1, o);
        }
        l0 = l0 * a0 + sum0;
        l1 = l1 * a1 + sum1;
        m0 = m0n; m1 = m1n;
        #pragma unroll
        for (int i = 0; i < 8; i++) { c0[i] *= a0; c1[i] *= a1; }
        __syncwarp();

        // PV: thread accumulates dims oct*8..oct*8+7 for its 2 rows
        #pragma unroll 4
        for (int j = 0; j < 64; j++) {
            float sv0 = Ss[r0 * 64 + j];
            float sv1 = Ss[r1 * 64 + j];
            float4 va = *(float4*)(Vt + j * 68 + oct * 8);
            float4 vb = *(float4*)(Vt + j * 68 + oct * 8 + 4);
            c0[0] += sv0*va.x; c0[1] += sv0*va.y; c0[2] += sv0*va.z; c0[3] += sv0*va.w;
            c0[4] += sv0*vb.x; c0[5] += sv0*vb.y; c0[6] += sv0*vb.z; c0[7] += sv0*vb.w;
            c1[0] += sv1*va.x; c1[1] += sv1*va.y; c1[2] += sv1*va.z; c1[3] += sv1*va.w;
            c1[4] += sv1*vb.x; c1[5] += sv1*vb.y; c1[6] += sv1*vb.z; c1[7] += sv1*vb.w;
        }
    }

    // epilogue: normalize, split to bf16 hi/lo, write
    float inv0 = 1.0f / l0, inv1 = 1.0f / l1;
    size_t off0 = (size_t)(bb * SS + q0 + r0) * DD + hh * DK + oct * 8;
    size_t off1 = (size_t)(bb * SS + q0 + r1) * DD + hh * DK + oct * 8;
    #pragma unroll
    for (int i = 0; i < 8; i += 2) {
        float x0 = c0[i] * inv0, x1 = c0[i+1] * inv0;
        __nv_bfloat162 H = split_hi2(x0, x1);
        __nv_bfloat162 L = split_lo2(x0, x1, H);
        *(__nv_bfloat162*)(ch + off0 + i) = H;
        *(__nv_bfloat162*)(cl + off0 + i) = L;
        float y0 = c1[i] * inv1, y1 = c1[i+1] * inv1;
        __nv_bfloat162 H1 = split_hi2(y0, y1);
        __nv_bfloat162 L1 = split_lo2(y0, y1, H1);
        *(__nv_bfloat162*)(ch + off1 + i) = H1;
        *(__nv_bfloat162*)(cl + off1 + i) = L1;
    }
}

// ---------------- host-side launch helpers ----------------
static void launch_split(const float* x, __nv_bfloat16* h, __nv_bfloat16* l, size_t n) {
    split_kernel<<<(unsigned)(n / 4 / 256), 256>>>(x, h, l);
}

static void launch_gemm1(const __nv_bfloat16* Ah, const __nv_bfloat16* Al,
                         const __nv_bfloat16* Wh, const __nv_bfloat16* Wl,
                         const float* bias, const float* res, float* C,
                         __nv_bfloat16* Ch, __nv_bfloat16* Cl,
                         int K, int N, int act) {
    GParams p{};
    p.Ah = Ah; p.Al = Al;
    p.Wh[0] = Wh; p.Wl[0] = Wl; p.bias[0] = bias; p.res[0] = res; p.C[0] = C;
    p.Ch = Ch; p.Cl = Cl;
    p.K = K; p.N = N; p.act = act;
    dim3 grid(N / BNT, MM / BMT, 1);
    gemm_bf16_kernel<<<grid, 256, GSMEM_TOTAL>>>(p);
}

extern "C" void kernel_launch(void* const* d_in, const int* in_sizes, int n_in,
                              void* d_out, int out_size) {
    const int*   x     = (const int*)d_in[0];
    const float* emb   = (const float*)d_in[1];
    const float* ln1_w = (const float*)d_in[2];
    const float* ln1_b = (const float*)d_in[3];
    const float* wq_w  = (const float*)d_in[4];
    const float* wq_b  = (const float*)d_in[5];
    const float* wk_w  = (const float*)d_in[6];
    const float* wk_b  = (const float*)d_in[7];
    const float* wv_w  = (const float*)d_in[8];
    const float* wv_b  = (const float*)d_in[9];
    const float* wo_w  = (const float*)d_in[10];
    const float* wo_b  = (const float*)d_in[11];
    const float* ln2_w = (const float*)d_in[12];
    const float* ln2_b = (const float*)d_in[13];
    const float* w1_w  = (const float*)d_in[14];
    const float* w1_b  = (const float*)d_in[15];
    const float* w2_w  = (const float*)d_in[16];
    const float* w2_b  = (const float*)d_in[17];
    const float* lnf_w = (const float*)d_in[18];
    const float* lnf_b = (const float*)d_in[19];
    float* out = (float*)d_out;

    cudaFuncSetAttribute(gemm_bf16_kernel, cudaFuncAttributeMaxDynamicSharedMemorySize,
                         GSMEM_TOTAL);
    cudaFuncSetAttribute(attn_kernel, cudaFuncAttributeMaxDynamicSharedMemorySize,
                         ASM_BYTES);

    float *h, *q, *k, *v;
    __nv_bfloat16 *ah, *al, *bh, *bl, *wh, *wl, *eh, *el;
    cudaGetSymbolAddress((void**)&h,  g_h);
    cudaGetSymbolAddress((void**)&q,  g_q);
    cudaGetSymbolAddress((void**)&k,  g_k);
    cudaGetSymbolAddress((void**)&v,  g_v);
    cudaGetSymbolAddress((void**)&ah, g_ah);
    cudaGetSymbolAddress((void**)&al, g_al);
    cudaGetSymbolAddress((void**)&bh, g_bh);
    cudaGetSymbolAddress((void**)&bl, g_bl);
    cudaGetSymbolAddress((void**)&wh, g_wh);
    cudaGetSymbolAddress((void**)&wl, g_wl);
    cudaGetSymbolAddress((void**)&eh, g_eh);
    cudaGetSymbolAddress((void**)&el, g_el);

    // split embedding once per call (tied output weights)
    launch_split(emb, eh, el, (size_t)VV * DD);

    embed_kernel<<<(MM * DD) / 256, 256>>>(x, emb, h);

    for (int l = 0; l < LL; l++) {
        size_t wdd = (size_t)l * DD * DD;
        ln_kernel<<<MM, 256>>>(h, ln1_w + (size_t)l * DD, ln1_b + (size_t)l * DD, ah, al);
        launch_split(wq_w + wdd, wh,            wl,            (size_t)DD * DD);
        launch_split(wk_w + wdd, wh + DD*DD,    wl + DD*DD,    (size_t)DD * DD);
        launch_split(wv_w + wdd, wh + 2*DD*DD,  wl + 2*DD*DD,  (size_t)DD * DD);

        {   // batched QKV gemm (z = 0,1,2)
            GParams p{};
            p.Ah = ah; p.Al = al;
            p.Wh[0] = wh;            p.Wl[0] = wl;
            p.Wh[1] = wh + DD*DD;    p.Wl[1] = wl + DD*DD;
            p.Wh[2] = wh + 2*DD*DD;  p.Wl[2] = wl + 2*DD*DD;
            p.bias[0] = wq_b + (size_t)l * DD;
            p.bias[1] = wk_b + (size_t)l * DD;
            p.bias[2] = wv_b + (size_t)l * DD;
            p.res[0] = p.res[1] = p.res[2] = nullptr;
            p.C[0] = q; p.C[1] = k; p.C[2] = v;
            p.Ch = nullptr; p.Cl = nullptr;
            p.K = DD; p.N = DD; p.act = 0;
            dim3 grid(DD / BNT, MM / BMT, 3);
            gemm_bf16_kernel<<<grid, 256, GSMEM_TOTAL>>>(p);
        }

        // flash attention -> ah/al (ctx in bf16 hi/lo)
        attn_kernel<<<dim3(SS / QT, BB * HH), 256, ASM_BYTES>>>(q, k, v, ah, al);

        // h = h + ctx @ Wo^T + bo
        launch_split(wo_w + wdd, wh, wl, (size_t)DD * DD);
        launch_gemm1(ah, al, wh, wl, wo_b + (size_t)l * DD, h, h, nullptr, nullptr, DD, DD, 0);

        ln_kernel<<<MM, 256>>>(h, ln2_w + (size_t)l * DD, ln2_b + (size_t)l * DD, ah, al);

        // ff = gelu(xn @ W1^T + b1) -> bf16 hi/lo directly
        launch_split(w1_w + (size_t)l * FFD * DD, wh, wl, (size_t)FFD * DD);
        launch_gemm1(ah, al, wh, wl, w1_b + (size_t)l * FFD, nullptr, nullptr, bh, bl, DD, FFD, 1);

        // h = h + ff @ W2^T + b2
        launch_split(w2_w + (size_t)l * DD * FFD, wh, wl, (size_t)DD * FFD);
        launch_gemm1(bh, bl, wh, wl, w2_b + (size_t)l * DD, h, h, nullptr, nullptr, FFD, DD, 0);
    }

    ln_kernel<<<MM, 256>>>(h, lnf_w, lnf_b, ah, al);

    // logits = xn @ emb^T (tied projection, no bias)
    launch_gemm1(ah, al, eh, el, nullptr, nullptr, out, nullptr, nullptr, DD, VV, 0);
}